// round 6
// baseline (speedup 1.0000x reference)
#include <cuda_runtime.h>
#include <math.h>
#include <float.h>

// Global accumulators for `load` (zero-initialized at module load; the last
// block of every launch resets them, keeping replays deterministic).
__device__ float    g_load[64];
__device__ unsigned g_ctr;

// ---------------------------------------------------------------------------
// Branchless top-2 update: value desc, scan order keeps earliest index on ties
// (strict > matches jax.lax.top_k).
// ---------------------------------------------------------------------------
__device__ __forceinline__ void upd2(float l, int gi,
                                     float& v0, int& i0, float& v1, int& i1)
{
    const bool p0 = l > v0;
    const bool p1 = l > v1;
    const float nv1 = p0 ? v0 : (p1 ? l : v1);
    const int   ni1 = p0 ? i0 : (p1 ? gi : i1);
    v0 = p0 ? l : v0;
    i0 = p0 ? gi : i0;
    v1 = nv1;
    i1 = ni1;
}

// ---------------------------------------------------------------------------
// Branchless symmetric merge of two sorted top-2 pairs under the total order
// (value desc, index asc). Both sides of a butterfly compute identical output.
// ---------------------------------------------------------------------------
__device__ __forceinline__ void merge2(float& v0, int& i0, float& v1, int& i1,
                                       float ov0, int oi0, float ov1, int oi1)
{
    const bool fw = (v0 > ov0) || (v0 == ov0 && i0 < oi0);
    const float w0  = fw ? v0  : ov0;
    const int   w0i = fw ? i0  : oi0;
    const float c   = fw ? ov0 : v0;
    const int   ci  = fw ? oi0 : i0;
    const float b   = fw ? v1  : ov1;
    const int   bi  = fw ? i1  : oi1;
    const bool  w   = (c > b) || (c == b && ci < bi);
    v0 = w0;  i0 = w0i;
    v1 = w ? c  : b;
    i1 = w ? ci : bi;
}

// ---------------------------------------------------------------------------
// Fused kernel: every block redundantly computes the 6-task gating tables
// (cheap: ~250 FMA/thread, weights L2-resident after wave 1), then runs the
// HBM-bound per-token gating loop. `load` via global accumulators + last-block
// writeback (threadfence + atomic counter).
// ---------------------------------------------------------------------------
__global__ __launch_bounds__(256, 5) void moe_gate_fused(
    const int*   __restrict__ taskID,
    const float* __restrict__ noise,
    const float* __restrict__ embed,   // (6, 32)
    const float* __restrict__ ekeys,   // (32, 32)
    const float* __restrict__ Wq,      // (32, 32)
    const float* __restrict__ bq,      // (32)
    const float* __restrict__ Wk,      // (32, 32)
    const float* __restrict__ bk,      // (32)
    const float* __restrict__ Wg,      // (64, 32)
    const float* __restrict__ bg,      // (64)
    const float* __restrict__ Wn,      // (64, 32)
    const float* __restrict__ bn,      // (64)
    float*       __restrict__ gates,
    float*       __restrict__ loadv,
    int B)
{
    __shared__ float s_wq[1024], s_wk[1024], s_ek[1024];
    __shared__ float s_wg[2048], s_wn[2048];
    __shared__ float s_q[6][32];
    __shared__ float s_k[32][32];
    __shared__ float s_ew[6][32];
    __shared__ float s_cl[6 * 64];
    __shared__ float s_st[6 * 64];
    __shared__ float s_load[64];
    __shared__ bool  s_last;

    const int tid = threadIdx.x;
    if (tid < 64) s_load[tid] = 0.0f;

    // ---- Prologue: per-block table computation -------------------------
    ((float4*)s_wq)[tid] = ((const float4*)Wq)[tid];
    ((float4*)s_wk)[tid] = ((const float4*)Wk)[tid];
    ((float4*)s_ek)[tid] = ((const float4*)ekeys)[tid];
    ((float4*)s_wg)[tid]       = ((const float4*)Wg)[tid];
    ((float4*)s_wg)[tid + 256] = ((const float4*)Wg)[tid + 256];
    ((float4*)s_wn)[tid]       = ((const float4*)Wn)[tid];
    ((float4*)s_wn)[tid + 256] = ((const float4*)Wn)[tid + 256];
    __syncthreads();

    // q[t][i] for all 6 tasks (threads 0..191)
    if (tid < 192) {
        const int t = tid >> 5, i = tid & 31;
        float acc = __ldg(bq + i);
        #pragma unroll
        for (int jj = 0; jj < 32; jj++)
            acc = fmaf(__ldg(embed + t * 32 + jj), s_wq[i * 32 + jj], acc);
        s_q[t][i] = acc * 0.35355339059327373f;   // 1/sqrt(8)
    }

    // k = expert_keys @ Wk^T + bk  (1024 entries; 256 threads x 4)
    {
        const int p0 = tid * 4;
        const int s = p0 >> 5;
        #pragma unroll
        for (int q = 0; q < 4; q++) {
            const int i = (p0 + q) & 31;
            float acc = __ldg(bk + i);
            #pragma unroll
            for (int jj = 0; jj < 32; jj++)
                acc = fmaf(s_ek[s * 32 + jj], s_wk[i * 32 + jj], acc);
            s_k[s][i] = acc;
        }
    }
    __syncthreads();

    // Warps 0..5: task w. Lanes = experts s. Scores, softmaxes, expert_weight.
    {
        const int w = tid >> 5, lane = tid & 31;
        if (w < 6) {
            float sc[4];
            #pragma unroll
            for (int h = 0; h < 4; h++) {
                float acc = 0.0f;
                #pragma unroll
                for (int d = 0; d < 8; d++)
                    acc = fmaf(s_q[w][h * 8 + d], s_k[lane][h * 8 + d], acc);
                sc[h] = acc;
            }
            float aw = 0.0f;
            #pragma unroll
            for (int h = 0; h < 4; h++) {
                float m = sc[h];
                #pragma unroll
                for (int d = 16; d; d >>= 1)
                    m = fmaxf(m, __shfl_xor_sync(0xffffffffu, m, d));
                float e = expf(sc[h] - m);
                float sum = e;
                #pragma unroll
                for (int d = 16; d; d >>= 1)
                    sum += __shfl_xor_sync(0xffffffffu, sum, d);
                aw += 0.25f * (e / sum);
            }
            float m2 = aw;
            #pragma unroll
            for (int d = 16; d; d >>= 1)
                m2 = fmaxf(m2, __shfl_xor_sync(0xffffffffu, m2, d));
            float e2 = expf(aw - m2);
            float s2 = e2;
            #pragma unroll
            for (int d = 16; d; d >>= 1)
                s2 += __shfl_xor_sync(0xffffffffu, s2, d);
            s_ew[w][lane] = e2 / s2;
        }
    }
    __syncthreads();

    // Tables: 384 entries over 256 threads (thread -> idx, idx+256).
    #pragma unroll
    for (int rep = 0; rep < 2; rep++) {
        const int idx = tid + rep * 256;
        if (idx < 384) {
            const int t = idx >> 6, e = idx & 63;
            float c  = __ldg(bg + e);
            float nv = __ldg(bn + e);
            #pragma unroll
            for (int s = 0; s < 32; s++) {
                const float w = s_ew[t][s];
                c  = fmaf(w, s_wg[e * 32 + s], c);
                nv = fmaf(w, s_wn[e * 32 + s], nv);
            }
            s_cl[idx] = c;
            const float sp = (nv > 0.0f) ? (nv + log1pf(expf(-nv)))
                                         : log1pf(expf(nv));
            s_st[idx] = sp + 0.01f;
        }
    }
    __syncthreads();

    // ---- Main loop: per-token gating, 8 lanes per token -----------------
    const int j = tid & 7;              // lane within octet
    const int oct4 = (tid >> 3) & 3;    // octet within warp
    const int base0 = j * 4;
    const int base1 = j * 4 + 32;
    const float4 z4 = make_float4(0.0f, 0.0f, 0.0f, 0.0f);

    const int tok0 = blockIdx.x * 256 + (tid >> 3);
    const float4* nq = (const float4*)(noise + (size_t)tok0 * 64) + j;
    float4*       gq = (float4*)      (gates + (size_t)tok0 * 64) + j;

    auto process = [&](const float4* nqi, float4* gqi, int t, unsigned mask) {
        gqi[0] = z4;
        gqi[8] = z4;
        const float4 n0 = nqi[0];
        const float4 n1 = nqi[8];

        const float4* cl4 = (const float4*)(s_cl + t * 64);
        const float4* st4 = (const float4*)(s_st + t * 64);
        const float4 c0 = cl4[j], c1 = cl4[j + 8];
        const float4 s0 = st4[j], s1 = st4[j + 8];

        const float l0 = fmaf(n0.x, s0.x, c0.x);
        const float l1 = fmaf(n0.y, s0.y, c0.y);
        const float l2 = fmaf(n0.z, s0.z, c0.z);
        const float l3 = fmaf(n0.w, s0.w, c0.w);
        const float l4 = fmaf(n1.x, s1.x, c1.x);
        const float l5 = fmaf(n1.y, s1.y, c1.y);
        const float l6 = fmaf(n1.z, s1.z, c1.z);
        const float l7 = fmaf(n1.w, s1.w, c1.w);

        float v0 = l0, v1 = -FLT_MAX;
        int i0 = base0, i1 = base0;
        upd2(l1, base0 + 1, v0, i0, v1, i1);
        upd2(l2, base0 + 2, v0, i0, v1, i1);
        upd2(l3, base0 + 3, v0, i0, v1, i1);
        upd2(l4, base1 + 0, v0, i0, v1, i1);
        upd2(l5, base1 + 1, v0, i0, v1, i1);
        upd2(l6, base1 + 2, v0, i0, v1, i1);
        upd2(l7, base1 + 3, v0, i0, v1, i1);

        #pragma unroll
        for (int d = 1; d < 8; d <<= 1) {
            const float ov0 = __shfl_xor_sync(mask, v0, d, 8);
            const int   oi0 = __shfl_xor_sync(mask, i0, d, 8);
            const float ov1 = __shfl_xor_sync(mask, v1, d, 8);
            const int   oi1 = __shfl_xor_sync(mask, i1, d, 8);
            merge2(v0, i0, v1, i1, ov0, oi0, ov1, oi1);
        }

        const float e  = __expf(v1 - v0);
        const float ga = __fdividef(1.0f, 1.0f + e);
        const float gb = e * ga;

        float* grow = (float*)(gqi - j);
        if (((i0 >> 2) & 7) == j) grow[i0] = ga;
        if (((i1 >> 2) & 7) == j) grow[i1] = gb;

        if (j == 0) {
            atomicAdd(&s_load[i0], ga);
            atomicAdd(&s_load[i1], gb);
        }
    };

    if ((blockIdx.x + 1) * 256 <= (unsigned)B) {
        // taskID preload: lane l holds task of token (warp*4 + (l&3) + 32*(l>>2))
        const int lane = tid & 31;
        const int pre = blockIdx.x * 256 + ((tid >> 5) << 2) +
                        (lane & 3) + ((lane >> 2) << 5);
        const int tval = __ldg(taskID + pre);
        #pragma unroll
        for (int it = 0; it < 8; ++it) {
            const int t = __shfl_sync(0xffffffffu, tval, it * 4 + oct4, 32);
            process(nq, gq, t, 0xffffffffu);
            nq += 512;          // 32 tokens * 16 float4
            gq += 512;
        }
    } else {
        const int* tp = taskID + tok0;
        int tok = tok0;
        for (int it = 0; it < 8; ++it) {
            const bool active = tok < B;
            const unsigned mask = __ballot_sync(0xffffffffu, active);
            if (active) {
                process(nq, gq, __ldg(tp), mask);
            }
            nq += 512;
            gq += 512;
            tp += 32;
            tok += 32;
        }
    }

    // ---- Epilogue: load accumulation + last-block writeback -------------
    __syncthreads();
    if (tid < 64) atomicAdd(&g_load[tid], s_load[tid]);
    __threadfence();
    __syncthreads();
    if (tid == 0) {
        const unsigned old = atomicAdd(&g_ctr, 1u);
        s_last = (old == gridDim.x - 1);
    }
    __syncthreads();
    if (s_last) {
        if (tid < 64) {
            volatile float* gl = g_load;
            loadv[tid] = gl[tid];
            g_load[tid] = 0.0f;       // reset for next (graph) replay
        }
        if (tid == 0) g_ctr = 0u;
    }
}

// ---------------------------------------------------------------------------
// Launch
// ---------------------------------------------------------------------------
extern "C" void kernel_launch(void* const* d_in, const int* in_sizes, int n_in,
                              void* d_out, int out_size)
{
    const int*   taskID = (const int*)  d_in[0];
    const float* noise  = (const float*)d_in[1];
    const float* embed  = (const float*)d_in[2];
    const float* ekeys  = (const float*)d_in[3];
    const float* Wq     = (const float*)d_in[4];
    const float* bq     = (const float*)d_in[5];
    const float* Wk     = (const float*)d_in[6];
    const float* bk     = (const float*)d_in[7];
    const float* Wg     = (const float*)d_in[8];
    const float* bg     = (const float*)d_in[9];
    const float* Wn     = (const float*)d_in[10];
    const float* bn     = (const float*)d_in[11];

    const int B = in_sizes[0];
    float* gates = (float*)d_out;
    float* loadv = (float*)d_out + (out_size - 64);  // load tail

    const int blocks = (B + 255) / 256;
    moe_gate_fused<<<blocks, 256>>>(taskID, noise, embed, ekeys,
                                    Wq, bq, Wk, bk, Wg, bg, Wn, bn,
                                    gates, loadv, B);
}

// round 7
// speedup vs baseline: 2.1490x; 2.1490x over previous
#include <cuda_runtime.h>
#include <math.h>
#include <float.h>

// Cross-block handshake state (zero-initialized; last block resets per launch
// so graph replays stay deterministic).
__device__ float    g_clean[384];
__device__ float    g_std[384];
__device__ unsigned g_flag;
__device__ unsigned g_ctr;

// ---------------------------------------------------------------------------
// Branchless top-2 update: value desc, scan order keeps earliest index on ties
// (strict > matches jax.lax.top_k).
// ---------------------------------------------------------------------------
__device__ __forceinline__ void upd2(float l, int gi,
                                     float& v0, int& i0, float& v1, int& i1)
{
    const bool p0 = l > v0;
    const bool p1 = l > v1;
    const float nv1 = p0 ? v0 : (p1 ? l : v1);
    const int   ni1 = p0 ? i0 : (p1 ? gi : i1);
    v0 = p0 ? l : v0;
    i0 = p0 ? gi : i0;
    v1 = nv1;
    i1 = ni1;
}

// ---------------------------------------------------------------------------
// Branchless symmetric merge of two sorted top-2 pairs under the total order
// (value desc, index asc). Both sides of a butterfly compute identical output.
// ---------------------------------------------------------------------------
__device__ __forceinline__ void merge2(float& v0, int& i0, float& v1, int& i1,
                                       float ov0, int oi0, float ov1, int oi1)
{
    const bool fw = (v0 > ov0) || (v0 == ov0 && i0 < oi0);
    const float w0  = fw ? v0  : ov0;
    const int   w0i = fw ? i0  : oi0;
    const float c   = fw ? ov0 : v0;
    const int   ci  = fw ? oi0 : i0;
    const float b   = fw ? v1  : ov1;
    const int   bi  = fw ? i1  : oi1;
    const bool  w   = (c > b) || (c == b && ci < bi);
    v0 = w0;  i0 = w0i;
    v1 = w ? c  : b;
    i1 = w ? ci : bi;
}

// ---------------------------------------------------------------------------
// Single fused kernel. Block 0 is the table producer (runs once, direct-LDG
// math, ~2-3us); all other blocks poll a flag, then run the HBM-bound gating
// loop. Tables travel via __device__ globals (L2).
// ---------------------------------------------------------------------------
__global__ __launch_bounds__(256) void moe_gate_fused(
    const int*   __restrict__ taskID,
    const float* __restrict__ noise,
    const float* __restrict__ embed,   // (6, 32)
    const float* __restrict__ ekeys,   // (32, 32)
    const float* __restrict__ Wq,      // (32, 32)
    const float* __restrict__ bq,      // (32)
    const float* __restrict__ Wk,      // (32, 32)
    const float* __restrict__ bk,      // (32)
    const float* __restrict__ Wg,      // (64, 32)
    const float* __restrict__ bg,      // (64)
    const float* __restrict__ Wn,      // (64, 32)
    const float* __restrict__ bn,      // (64)
    float*       __restrict__ gates,
    float*       __restrict__ loadv,
    int B)
{
    __shared__ float s_cl[384];
    __shared__ float s_st[384];
    __shared__ float s_load[64];
    __shared__ float s_q[6][32];
    __shared__ float s_k[32][32];
    __shared__ float s_ew[6][32];
    __shared__ bool  s_last;

    const int tid = threadIdx.x;
    if (tid < 64) s_load[tid] = 0.0f;

    // Token geometry (needed early for prefetch).
    const int j = tid & 7;               // lane within octet
    const int oct4 = (tid >> 3) & 3;     // octet within warp
    const int base0 = j * 4;
    const int base1 = j * 4 + 32;
    const int tok0 = blockIdx.x * 256 + (tid >> 3);
    const float4* nq = (const float4*)(noise + (size_t)tok0 * 64) + j;
    float4*       gq = (float4*)      (gates + (size_t)tok0 * 64) + j;
    const bool full = (blockIdx.x + 1) * 256 <= (unsigned)B;

    // Prefetch first iterations' noise into L2 (overlaps with flag spin).
    if (full) {
        asm volatile("prefetch.global.L2 [%0];" :: "l"(nq));
        asm volatile("prefetch.global.L2 [%0];" :: "l"(nq + 8));
        asm volatile("prefetch.global.L2 [%0];" :: "l"(nq + 512));
        asm volatile("prefetch.global.L2 [%0];" :: "l"(nq + 520));
    }

    if (blockIdx.x == 0) {
        // ---------------- Producer: compute tables once ----------------
        if (tid < 64) loadv[tid] = 0.0f;

        // q[t][i] for all 6 tasks (threads 0..191)
        if (tid < 192) {
            const int t = tid >> 5, i = tid & 31;
            float acc = __ldg(bq + i);
            #pragma unroll
            for (int jj = 0; jj < 32; jj++)
                acc = fmaf(__ldg(embed + t * 32 + jj),
                           __ldg(Wq + i * 32 + jj), acc);
            s_q[t][i] = acc * 0.35355339059327373f;   // 1/sqrt(8)
        }
        // k = expert_keys @ Wk^T + bk (1024 entries; 256 threads x 4)
        {
            const int p0 = tid * 4;
            const int s = p0 >> 5;
            #pragma unroll
            for (int q = 0; q < 4; q++) {
                const int i = (p0 + q) & 31;
                float acc = __ldg(bk + i);
                #pragma unroll
                for (int jj = 0; jj < 32; jj++)
                    acc = fmaf(__ldg(ekeys + s * 32 + jj),
                               __ldg(Wk + i * 32 + jj), acc);
                s_k[s][i] = acc;
            }
        }
        __syncthreads();

        // Warps 0..5 (task w), lanes = experts: softmaxes -> expert_weight.
        {
            const int w = tid >> 5, lane = tid & 31;
            if (w < 6) {
                float sc[4];
                #pragma unroll
                for (int h = 0; h < 4; h++) {
                    float acc = 0.0f;
                    #pragma unroll
                    for (int d = 0; d < 8; d++)
                        acc = fmaf(s_q[w][h * 8 + d], s_k[lane][h * 8 + d], acc);
                    sc[h] = acc;
                }
                float aw = 0.0f;
                #pragma unroll
                for (int h = 0; h < 4; h++) {
                    float m = sc[h];
                    #pragma unroll
                    for (int d = 16; d; d >>= 1)
                        m = fmaxf(m, __shfl_xor_sync(0xffffffffu, m, d));
                    float e = expf(sc[h] - m);
                    float sum = e;
                    #pragma unroll
                    for (int d = 16; d; d >>= 1)
                        sum += __shfl_xor_sync(0xffffffffu, sum, d);
                    aw += 0.25f * (e / sum);
                }
                float m2 = aw;
                #pragma unroll
                for (int d = 16; d; d >>= 1)
                    m2 = fmaxf(m2, __shfl_xor_sync(0xffffffffu, m2, d));
                float e2 = expf(aw - m2);
                float s2 = e2;
                #pragma unroll
                for (int d = 16; d; d >>= 1)
                    s2 += __shfl_xor_sync(0xffffffffu, s2, d);
                s_ew[w][lane] = e2 / s2;
            }
        }
        __syncthreads();

        // Tables: 384 entries; publish to smem + global.
        #pragma unroll
        for (int rep = 0; rep < 2; rep++) {
            const int idx = tid + rep * 256;
            if (idx < 384) {
                const int t = idx >> 6, e = idx & 63;
                float c  = __ldg(bg + e);
                float nv = __ldg(bn + e);
                #pragma unroll
                for (int s = 0; s < 32; s++) {
                    const float w = s_ew[t][s];
                    c  = fmaf(w, __ldg(Wg + e * 32 + s), c);
                    nv = fmaf(w, __ldg(Wn + e * 32 + s), nv);
                }
                s_cl[idx] = c;
                g_clean[idx] = c;
                const float sp = (nv > 0.0f) ? (nv + log1pf(expf(-nv)))
                                             : log1pf(expf(nv));
                s_st[idx] = sp + 0.01f;
                g_std[idx] = sp + 0.01f;
            }
        }
        __syncthreads();
        __threadfence();
        if (tid == 0) atomicExch(&g_flag, 1u);
    } else {
        // ---------------- Consumers: wait, then pull tables ----------------
        if (tid == 0) {
            while (atomicAdd(&g_flag, 0u) == 0u) __nanosleep(64);
        }
        __syncthreads();
        __threadfence();   // acquire: order table reads after flag observation
        for (int i = tid; i < 384; i += 256) {
            s_cl[i] = g_clean[i];
            s_st[i] = g_std[i];
        }
        __syncthreads();
    }

    // ---------------- Gate main loop: 8 lanes per token ----------------
    const float4 z4 = make_float4(0.0f, 0.0f, 0.0f, 0.0f);

    auto process = [&](const float4* nqi, float4* gqi, int t, unsigned mask) {
        gqi[0] = z4;
        gqi[8] = z4;
        const float4 n0 = nqi[0];
        const float4 n1 = nqi[8];

        const float4* cl4 = (const float4*)(s_cl + t * 64);
        const float4* st4 = (const float4*)(s_st + t * 64);
        const float4 c0 = cl4[j], c1 = cl4[j + 8];
        const float4 s0 = st4[j], s1 = st4[j + 8];

        const float l0 = fmaf(n0.x, s0.x, c0.x);
        const float l1 = fmaf(n0.y, s0.y, c0.y);
        const float l2 = fmaf(n0.z, s0.z, c0.z);
        const float l3 = fmaf(n0.w, s0.w, c0.w);
        const float l4 = fmaf(n1.x, s1.x, c1.x);
        const float l5 = fmaf(n1.y, s1.y, c1.y);
        const float l6 = fmaf(n1.z, s1.z, c1.z);
        const float l7 = fmaf(n1.w, s1.w, c1.w);

        float v0 = l0, v1 = -FLT_MAX;
        int i0 = base0, i1 = base0;
        upd2(l1, base0 + 1, v0, i0, v1, i1);
        upd2(l2, base0 + 2, v0, i0, v1, i1);
        upd2(l3, base0 + 3, v0, i0, v1, i1);
        upd2(l4, base1 + 0, v0, i0, v1, i1);
        upd2(l5, base1 + 1, v0, i0, v1, i1);
        upd2(l6, base1 + 2, v0, i0, v1, i1);
        upd2(l7, base1 + 3, v0, i0, v1, i1);

        #pragma unroll
        for (int d = 1; d < 8; d <<= 1) {
            const float ov0 = __shfl_xor_sync(mask, v0, d, 8);
            const int   oi0 = __shfl_xor_sync(mask, i0, d, 8);
            const float ov1 = __shfl_xor_sync(mask, v1, d, 8);
            const int   oi1 = __shfl_xor_sync(mask, i1, d, 8);
            merge2(v0, i0, v1, i1, ov0, oi0, ov1, oi1);
        }

        const float e  = __expf(v1 - v0);
        const float ga = __fdividef(1.0f, 1.0f + e);
        const float gb = e * ga;

        float* grow = (float*)(gqi - j);
        if (((i0 >> 2) & 7) == j) grow[i0] = ga;
        if (((i1 >> 2) & 7) == j) grow[i1] = gb;

        if (j == 0) {
            atomicAdd(&s_load[i0], ga);
            atomicAdd(&s_load[i1], gb);
        }
    };

    if (full) {
        // taskID preload: lane l holds task of token (warp*4 + (l&3) + 32*(l>>2))
        const int lane = tid & 31;
        const int pre = blockIdx.x * 256 + ((tid >> 5) << 2) +
                        (lane & 3) + ((lane >> 2) << 5);
        const int tval = __ldg(taskID + pre);
        const float4* nqi = nq;
        float4* gqi = gq;
        #pragma unroll
        for (int it = 0; it < 8; ++it) {
            const int t = __shfl_sync(0xffffffffu, tval, it * 4 + oct4, 32);
            process(nqi, gqi, t, 0xffffffffu);
            nqi += 512;          // 32 tokens * 16 float4
            gqi += 512;
        }
    } else {
        const int* tp = taskID + tok0;
        const float4* nqi = nq;
        float4* gqi = gq;
        int tok = tok0;
        for (int it = 0; it < 8; ++it) {
            const bool active = tok < B;
            const unsigned mask = __ballot_sync(0xffffffffu, active);
            if (active) {
                process(nqi, gqi, __ldg(tp), mask);
            }
            nqi += 512;
            gqi += 512;
            tp += 32;
            tok += 32;
        }
    }

    // ---------------- Epilogue: load accumulation + reset ----------------
    __syncthreads();
    if (tid < 64) atomicAdd(&loadv[tid], s_load[tid]);
    __threadfence();
    __syncthreads();
    if (tid == 0) {
        const unsigned old = atomicAdd(&g_ctr, 1u);
        s_last = (old == gridDim.x - 1);
    }
    __syncthreads();
    if (s_last && tid == 0) {
        g_flag = 0u;       // reset handshake for next graph replay
        g_ctr = 0u;
    }
}

// ---------------------------------------------------------------------------
// Launch
// ---------------------------------------------------------------------------
extern "C" void kernel_launch(void* const* d_in, const int* in_sizes, int n_in,
                              void* d_out, int out_size)
{
    const int*   taskID = (const int*)  d_in[0];
    const float* noise  = (const float*)d_in[1];
    const float* embed  = (const float*)d_in[2];
    const float* ekeys  = (const float*)d_in[3];
    const float* Wq     = (const float*)d_in[4];
    const float* bq     = (const float*)d_in[5];
    const float* Wk     = (const float*)d_in[6];
    const float* bk     = (const float*)d_in[7];
    const float* Wg     = (const float*)d_in[8];
    const float* bg     = (const float*)d_in[9];
    const float* Wn     = (const float*)d_in[10];
    const float* bn     = (const float*)d_in[11];

    const int B = in_sizes[0];
    float* gates = (float*)d_out;
    float* loadv = (float*)d_out + (out_size - 64);  // load tail

    const int blocks = (B + 255) / 256;
    moe_gate_fused<<<blocks, 256>>>(taskID, noise, embed, ekeys,
                                    Wq, bq, Wk, bk, Wg, bg, Wn, bn,
                                    gates, loadv, B);
}

// round 8
// speedup vs baseline: 2.4593x; 1.1444x over previous
#include <cuda_runtime.h>
#include <math.h>
#include <float.h>

// Tables computed once by the 1-block primary kernel, consumed by the grid.
__device__ float g_clean[384];
__device__ float g_std[384];

// ---------------------------------------------------------------------------
// Kernel 1 (primary, 1 block x 256): compute the 6x64 clean/std tables,
// zero loadv, then trigger the dependent launch.
// ---------------------------------------------------------------------------
__global__ __launch_bounds__(256) void precompute_kernel(
    const float* __restrict__ embed,   // (6, 32)
    const float* __restrict__ ekeys,   // (32, 32)
    const float* __restrict__ Wq,      // (32, 32)
    const float* __restrict__ bq,      // (32)
    const float* __restrict__ Wk,      // (32, 32)
    const float* __restrict__ bk,      // (32)
    const float* __restrict__ Wg,      // (64, 32)
    const float* __restrict__ bg,      // (64)
    const float* __restrict__ Wn,      // (64, 32)
    const float* __restrict__ bn,      // (64)
    float* __restrict__ load_out)      // (64) -> zero it
{
    const int tid = threadIdx.x;

    __shared__ float s_q[6][32];
    __shared__ float s_k[32][32];
    __shared__ float s_ew[6][32];

    if (tid < 64) load_out[tid] = 0.0f;

    // q[t][i] for all 6 tasks (threads 0..191)
    if (tid < 192) {
        const int t = tid >> 5, i = tid & 31;
        float acc = __ldg(bq + i);
        #pragma unroll
        for (int jj = 0; jj < 32; jj++)
            acc = fmaf(__ldg(embed + t * 32 + jj),
                       __ldg(Wq + i * 32 + jj), acc);
        s_q[t][i] = acc * 0.35355339059327373f;   // 1/sqrt(8)
    }
    // k = expert_keys @ Wk^T + bk (1024 entries; 256 threads x 4)
    {
        const int p0 = tid * 4;
        const int s = p0 >> 5;
        #pragma unroll
        for (int q = 0; q < 4; q++) {
            const int i = (p0 + q) & 31;
            float acc = __ldg(bk + i);
            #pragma unroll
            for (int jj = 0; jj < 32; jj++)
                acc = fmaf(__ldg(ekeys + s * 32 + jj),
                           __ldg(Wk + i * 32 + jj), acc);
            s_k[s][i] = acc;
        }
    }
    __syncthreads();

    // Warps 0..5 (task w), lanes = experts: softmaxes -> expert_weight.
    {
        const int w = tid >> 5, lane = tid & 31;
        if (w < 6) {
            float sc[4];
            #pragma unroll
            for (int h = 0; h < 4; h++) {
                float acc = 0.0f;
                #pragma unroll
                for (int d = 0; d < 8; d++)
                    acc = fmaf(s_q[w][h * 8 + d], s_k[lane][h * 8 + d], acc);
                sc[h] = acc;
            }
            float aw = 0.0f;
            #pragma unroll
            for (int h = 0; h < 4; h++) {
                float m = sc[h];
                #pragma unroll
                for (int d = 16; d; d >>= 1)
                    m = fmaxf(m, __shfl_xor_sync(0xffffffffu, m, d));
                float e = expf(sc[h] - m);
                float sum = e;
                #pragma unroll
                for (int d = 16; d; d >>= 1)
                    sum += __shfl_xor_sync(0xffffffffu, sum, d);
                aw += 0.25f * (e / sum);
            }
            float m2 = aw;
            #pragma unroll
            for (int d = 16; d; d >>= 1)
                m2 = fmaxf(m2, __shfl_xor_sync(0xffffffffu, m2, d));
            float e2 = expf(aw - m2);
            float s2 = e2;
            #pragma unroll
            for (int d = 16; d; d >>= 1)
                s2 += __shfl_xor_sync(0xffffffffu, s2, d);
            s_ew[w][lane] = e2 / s2;
        }
    }
    __syncthreads();

    // Tables: 384 entries -> __device__ globals.
    #pragma unroll
    for (int rep = 0; rep < 2; rep++) {
        const int idx = tid + rep * 256;
        if (idx < 384) {
            const int t = idx >> 6, e = idx & 63;
            float c  = __ldg(bg + e);
            float nv = __ldg(bn + e);
            #pragma unroll
            for (int s = 0; s < 32; s++) {
                const float w = s_ew[t][s];
                c  = fmaf(w, __ldg(Wg + e * 32 + s), c);
                nv = fmaf(w, __ldg(Wn + e * 32 + s), nv);
            }
            g_clean[idx] = c;
            const float sp = (nv > 0.0f) ? (nv + log1pf(expf(-nv)))
                                         : log1pf(expf(nv));
            g_std[idx] = sp + 0.01f;
        }
    }
    __threadfence();
    __syncthreads();
    cudaTriggerProgrammaticLaunchCompletion();
}

// ---------------------------------------------------------------------------
// Branchless top-2 update: value desc, scan order keeps earliest index on ties
// (strict > matches jax.lax.top_k).
// ---------------------------------------------------------------------------
__device__ __forceinline__ void upd2(float l, int gi,
                                     float& v0, int& i0, float& v1, int& i1)
{
    const bool p0 = l > v0;
    const bool p1 = l > v1;
    const float nv1 = p0 ? v0 : (p1 ? l : v1);
    const int   ni1 = p0 ? i0 : (p1 ? gi : i1);
    v0 = p0 ? l : v0;
    i0 = p0 ? gi : i0;
    v1 = nv1;
    i1 = ni1;
}

// ---------------------------------------------------------------------------
// Branchless symmetric merge of two sorted top-2 pairs under the total order
// (value desc, index asc). Both sides of a butterfly compute identical output.
// ---------------------------------------------------------------------------
__device__ __forceinline__ void merge2(float& v0, int& i0, float& v1, int& i1,
                                       float ov0, int oi0, float ov1, int oi1)
{
    const bool fw = (v0 > ov0) || (v0 == ov0 && i0 < oi0);
    const float w0  = fw ? v0  : ov0;
    const int   w0i = fw ? i0  : oi0;
    const float c   = fw ? ov0 : v0;
    const int   ci  = fw ? oi0 : i0;
    const float b   = fw ? v1  : ov1;
    const int   bi  = fw ? i1  : oi1;
    const bool  w   = (c > b) || (c == b && ci < bi);
    v0 = w0;  i0 = w0i;
    v1 = w ? c  : b;
    i1 = w ? ci : bi;
}

// ---------------------------------------------------------------------------
// Kernel 2 (secondary, PDL): per-token gating, 8 lanes per token.
// Prefetches its first noise lines into L2 BEFORE the grid dependency sync,
// then pulls the 3KB tables from L2 and runs the HBM-bound loop.
// ---------------------------------------------------------------------------
__global__ __launch_bounds__(256, 6) void gate_kernel(
    const int*   __restrict__ taskID,
    const float* __restrict__ noise,
    float*       __restrict__ gates,
    float*       __restrict__ loadv,
    int B)
{
    __shared__ float s_cl[384];
    __shared__ float s_st[384];
    __shared__ float s_load[64];

    const int tid = threadIdx.x;
    if (tid < 64) s_load[tid] = 0.0f;

    const int j = tid & 7;               // lane within octet
    const int oct4 = (tid >> 3) & 3;     // octet within warp
    const int base0 = j * 4;
    const int base1 = j * 4 + 32;
    const int tok0 = blockIdx.x * 256 + (tid >> 3);
    const float4* nq = (const float4*)(noise + (size_t)tok0 * 64) + j;
    float4*       gq = (float4*)      (gates + (size_t)tok0 * 64) + j;
    const bool full = (blockIdx.x + 1) * 256 <= (unsigned)B;

    // Overlap: warm L2 with this block's first noise lines while the
    // primary kernel finishes.
    if (full) {
        asm volatile("prefetch.global.L2 [%0];" :: "l"(nq));
        asm volatile("prefetch.global.L2 [%0];" :: "l"(nq + 8));
        asm volatile("prefetch.global.L2 [%0];" :: "l"(nq + 512));
        asm volatile("prefetch.global.L2 [%0];" :: "l"(nq + 520));
    }

    cudaGridDependencySynchronize();   // primary's writes now visible

    for (int i = tid; i < 384; i += 256) {
        s_cl[i] = g_clean[i];
        s_st[i] = g_std[i];
    }
    __syncthreads();

    const float4 z4 = make_float4(0.0f, 0.0f, 0.0f, 0.0f);

    auto process = [&](const float4* nqi, float4* gqi, int t, unsigned mask) {
        gqi[0] = z4;
        gqi[8] = z4;
        const float4 n0 = nqi[0];
        const float4 n1 = nqi[8];

        const float4* cl4 = (const float4*)(s_cl + t * 64);
        const float4* st4 = (const float4*)(s_st + t * 64);
        const float4 c0 = cl4[j], c1 = cl4[j + 8];
        const float4 s0 = st4[j], s1 = st4[j + 8];

        const float l0 = fmaf(n0.x, s0.x, c0.x);
        const float l1 = fmaf(n0.y, s0.y, c0.y);
        const float l2 = fmaf(n0.z, s0.z, c0.z);
        const float l3 = fmaf(n0.w, s0.w, c0.w);
        const float l4 = fmaf(n1.x, s1.x, c1.x);
        const float l5 = fmaf(n1.y, s1.y, c1.y);
        const float l6 = fmaf(n1.z, s1.z, c1.z);
        const float l7 = fmaf(n1.w, s1.w, c1.w);

        float v0 = l0, v1 = -FLT_MAX;
        int i0 = base0, i1 = base0;
        upd2(l1, base0 + 1, v0, i0, v1, i1);
        upd2(l2, base0 + 2, v0, i0, v1, i1);
        upd2(l3, base0 + 3, v0, i0, v1, i1);
        upd2(l4, base1 + 0, v0, i0, v1, i1);
        upd2(l5, base1 + 1, v0, i0, v1, i1);
        upd2(l6, base1 + 2, v0, i0, v1, i1);
        upd2(l7, base1 + 3, v0, i0, v1, i1);

        #pragma unroll
        for (int d = 1; d < 8; d <<= 1) {
            const float ov0 = __shfl_xor_sync(mask, v0, d, 8);
            const int   oi0 = __shfl_xor_sync(mask, i0, d, 8);
            const float ov1 = __shfl_xor_sync(mask, v1, d, 8);
            const int   oi1 = __shfl_xor_sync(mask, i1, d, 8);
            merge2(v0, i0, v1, i1, ov0, oi0, ov1, oi1);
        }

        const float e  = __expf(v1 - v0);
        const float ga = __fdividef(1.0f, 1.0f + e);
        const float gb = e * ga;

        float* grow = (float*)(gqi - j);
        if (((i0 >> 2) & 7) == j) grow[i0] = ga;
        if (((i1 >> 2) & 7) == j) grow[i1] = gb;

        if (j == 0) {
            atomicAdd(&s_load[i0], ga);
            atomicAdd(&s_load[i1], gb);
        }
    };

    if (full) {
        // taskID preload: lane l holds task of token (warp*4 + (l&3) + 32*(l>>2))
        const int lane = tid & 31;
        const int pre = blockIdx.x * 256 + ((tid >> 5) << 2) +
                        (lane & 3) + ((lane >> 2) << 5);
        const int tval = __ldg(taskID + pre);
        const float4* nqi = nq;
        float4* gqi = gq;
        #pragma unroll
        for (int it = 0; it < 8; ++it) {
            const int t = __shfl_sync(0xffffffffu, tval, it * 4 + oct4, 32);
            process(nqi, gqi, t, 0xffffffffu);
            nqi += 512;          // 32 tokens * 16 float4
            gqi += 512;
        }
    } else {
        const int* tp = taskID + tok0;
        const float4* nqi = nq;
        float4* gqi = gq;
        int tok = tok0;
        for (int it = 0; it < 8; ++it) {
            const bool active = tok < B;
            const unsigned mask = __ballot_sync(0xffffffffu, active);
            if (active) {
                process(nqi, gqi, __ldg(tp), mask);
            }
            nqi += 512;
            gqi += 512;
            tp += 32;
            tok += 32;
        }
    }

    __syncthreads();
    if (tid < 64) atomicAdd(&loadv[tid], s_load[tid]);
}

// ---------------------------------------------------------------------------
// Launch: primary normally, secondary via PDL (programmatic stream
// serialization) so its blocks schedule/prefetch while the primary runs.
// ---------------------------------------------------------------------------
extern "C" void kernel_launch(void* const* d_in, const int* in_sizes, int n_in,
                              void* d_out, int out_size)
{
    const int*   taskID = (const int*)  d_in[0];
    const float* noise  = (const float*)d_in[1];
    const float* embed  = (const float*)d_in[2];
    const float* ekeys  = (const float*)d_in[3];
    const float* Wq     = (const float*)d_in[4];
    const float* bq     = (const float*)d_in[5];
    const float* Wk     = (const float*)d_in[6];
    const float* bk     = (const float*)d_in[7];
    const float* Wg     = (const float*)d_in[8];
    const float* bg     = (const float*)d_in[9];
    const float* Wn     = (const float*)d_in[10];
    const float* bn     = (const float*)d_in[11];

    const int B = in_sizes[0];
    float* gates = (float*)d_out;
    float* loadv = (float*)d_out + (out_size - 64);  // load tail

    precompute_kernel<<<1, 256>>>(embed, ekeys, Wq, bq, Wk, bk,
                                  Wg, bg, Wn, bn, loadv);

    const int blocks = (B + 255) / 256;

    cudaLaunchConfig_t cfg = {};
    cfg.gridDim  = dim3((unsigned)blocks, 1, 1);
    cfg.blockDim = dim3(256, 1, 1);
    cfg.dynamicSmemBytes = 0;
    cfg.stream = 0;
    cudaLaunchAttribute attrs[1];
    attrs[0].id = cudaLaunchAttributeProgrammaticStreamSerialization;
    attrs[0].val.programmaticStreamSerializationAllowed = 1;
    cfg.attrs = attrs;
    cfg.numAttrs = 1;

    cudaLaunchKernelEx(&cfg, gate_kernel, taskID, noise, gates, loadv, B);
}

// round 9
// speedup vs baseline: 3.2403x; 1.3176x over previous
#include <cuda_runtime.h>
#include <math.h>
#include <float.h>

// Per-task precomputed gating tables: only 6 distinct taskIDs exist.
__device__ float g_clean[6 * 64];
__device__ float g_std[6 * 64];

// ---------------------------------------------------------------------------
// Kernel 1: per-task precompute (6 blocks x 256 threads). All weights staged
// in shared via coalesced float4 loads.
// ---------------------------------------------------------------------------
__global__ __launch_bounds__(256) void precompute_kernel(
    const float* __restrict__ embed,   // (6, 32)
    const float* __restrict__ ekeys,   // (32, 32)
    const float* __restrict__ Wq,      // (32, 32)
    const float* __restrict__ bq,      // (32)
    const float* __restrict__ Wk,      // (32, 32)
    const float* __restrict__ bk,      // (32)
    const float* __restrict__ Wg,      // (64, 32)
    const float* __restrict__ bg,      // (64)
    const float* __restrict__ Wn,      // (64, 32)
    const float* __restrict__ bn,      // (64)
    float* __restrict__ load_out)      // (64) -> zero it
{
    const int t = blockIdx.x;
    const int tid = threadIdx.x;

    __shared__ float s_wq[1024], s_wk[1024], s_ek[1024];
    __shared__ float s_wg[2048], s_wn[2048];
    __shared__ float s_q[32];
    __shared__ float s_k[32][32];
    __shared__ float s_ew[32];

    if (t == 0 && tid < 64) load_out[tid] = 0.0f;

    // Stage weights (coalesced float4)
    ((float4*)s_wq)[tid] = ((const float4*)Wq)[tid];
    ((float4*)s_wk)[tid] = ((const float4*)Wk)[tid];
    ((float4*)s_ek)[tid] = ((const float4*)ekeys)[tid];
    ((float4*)s_wg)[tid]       = ((const float4*)Wg)[tid];
    ((float4*)s_wg)[tid + 256] = ((const float4*)Wg)[tid + 256];
    ((float4*)s_wn)[tid]       = ((const float4*)Wn)[tid];
    ((float4*)s_wn)[tid + 256] = ((const float4*)Wn)[tid + 256];
    __syncthreads();

    // q = (embed[t] @ Wq^T + bq) * 1/sqrt(8)
    if (tid < 32) {
        float acc = bq[tid];
        #pragma unroll
        for (int jj = 0; jj < 32; jj++)
            acc = fmaf(embed[t * 32 + jj], s_wq[tid * 32 + jj], acc);
        s_q[tid] = acc * 0.35355339059327373f;
    }

    // k = expert_keys @ Wk^T + bk  (1024 entries; 256 threads x 4)
    {
        const int p0 = tid * 4;
        const int s = p0 >> 5;
        #pragma unroll
        for (int q = 0; q < 4; q++) {
            const int i = (p0 + q) & 31;
            float acc = bk[i];
            #pragma unroll
            for (int jj = 0; jj < 32; jj++)
                acc = fmaf(s_ek[s * 32 + jj], s_wk[i * 32 + jj], acc);
            s_k[s][i] = acc;
        }
    }
    __syncthreads();

    // Warp 0 (lanes = experts s): scores, per-head softmax, mean, softmax.
    if (tid < 32) {
        float sc[4];
        #pragma unroll
        for (int h = 0; h < 4; h++) {
            float acc = 0.0f;
            #pragma unroll
            for (int d = 0; d < 8; d++)
                acc = fmaf(s_q[h * 8 + d], s_k[tid][h * 8 + d], acc);
            sc[h] = acc;
        }
        float aw = 0.0f;
        #pragma unroll
        for (int h = 0; h < 4; h++) {
            float m = sc[h];
            #pragma unroll
            for (int d = 16; d; d >>= 1)
                m = fmaxf(m, __shfl_xor_sync(0xffffffffu, m, d));
            float e = expf(sc[h] - m);
            float sum = e;
            #pragma unroll
            for (int d = 16; d; d >>= 1)
                sum += __shfl_xor_sync(0xffffffffu, sum, d);
            aw += 0.25f * (e / sum);
        }
        float m2 = aw;
        #pragma unroll
        for (int d = 16; d; d >>= 1)
            m2 = fmaxf(m2, __shfl_xor_sync(0xffffffffu, m2, d));
        float e2 = expf(aw - m2);
        float s2 = e2;
        #pragma unroll
        for (int d = 16; d; d >>= 1)
            s2 += __shfl_xor_sync(0xffffffffu, s2, d);
        s_ew[tid] = e2 / s2;
    }
    __syncthreads();

    // clean_logits[e], noise_std[e]; threads 0..63
    if (tid < 64) {
        float c = bg[tid];
        float nv = bn[tid];
        #pragma unroll
        for (int s = 0; s < 32; s++) {
            const float w = s_ew[s];
            c  = fmaf(w, s_wg[tid * 32 + s], c);
            nv = fmaf(w, s_wn[tid * 32 + s], nv);
        }
        g_clean[t * 64 + tid] = c;
        const float sp = (nv > 0.0f) ? (nv + log1pf(expf(-nv)))
                                     : log1pf(expf(nv));
        g_std[t * 64 + tid] = sp + 0.01f;
    }
}

// ---------------------------------------------------------------------------
// Merge two SORTED top-2 pairs where ALL indices of pair A are lower than all
// indices of pair B. Ties then need only '>=' (prefers the lower-index side):
//   winner: a0 >= b0 keeps A on tie (lower index)     [jax.lax.top_k]
//   second: candidate x is always the A-side element, so x >= y keeps the
//           lower index on tie.
// ---------------------------------------------------------------------------
__device__ __forceinline__ void merge_sorted_lowhi(
    float a0, int ia0, float a1, int ia1,
    float b0, int ib0, float b1, int ib1,
    float& v0, int& i0, float& v1, int& i1)
{
    const bool p = a0 >= b0;
    v0 = fmaxf(a0, b0);
    i0 = p ? ia0 : ib0;
    const float x  = p ? a1 : a0;   // A-side candidate (lower index)
    const int   xi = p ? ia1 : ia0;
    const float y  = p ? b0 : b1;
    const int   yi = p ? ib0 : ib1;
    const bool q = x >= y;
    v1 = fmaxf(x, y);
    i1 = q ? xi : yi;
}

// ---------------------------------------------------------------------------
// Branchless symmetric merge of two sorted top-2 pairs under the total order
// (value desc, index asc). Both sides of a butterfly compute identical output.
// (Index sets interleave across lanes, so full tie logic is required here.)
// ---------------------------------------------------------------------------
__device__ __forceinline__ void merge2(float& v0, int& i0, float& v1, int& i1,
                                       float ov0, int oi0, float ov1, int oi1)
{
    const bool fw = (v0 > ov0) || (v0 == ov0 && i0 < oi0);
    const float w0  = fw ? v0  : ov0;
    const int   w0i = fw ? i0  : oi0;
    const float c   = fw ? ov0 : v0;
    const int   ci  = fw ? oi0 : i0;
    const float b   = fw ? v1  : ov1;
    const int   bi  = fw ? i1  : oi1;
    const bool  w   = (c > b) || (c == b && ci < bi);
    v0 = w0;  i0 = w0i;
    v1 = w ? c  : b;
    i1 = w ? ci : bi;
}

// ---------------------------------------------------------------------------
// Kernel 2: per-token gating, 8 lanes per token (perfect 128B coalescing).
// Local top-2 via tournament tree (sorted-pair merges with cheap exact ties).
// ---------------------------------------------------------------------------
__global__ __launch_bounds__(256) void gate_kernel(
    const int*   __restrict__ taskID,
    const float* __restrict__ noise,
    float*       __restrict__ gates,
    float*       __restrict__ loadv,
    int B)
{
    __shared__ float s_cl[6 * 64];
    __shared__ float s_st[6 * 64];
    __shared__ float s_load[64];

    const int tid = threadIdx.x;
    if (tid < 64) s_load[tid] = 0.0f;
    for (int i = tid; i < 6 * 64; i += 256) {
        s_cl[i] = g_clean[i];
        s_st[i] = g_std[i];
    }
    __syncthreads();

    const int j = tid & 7;              // lane within octet
    const int base0 = j * 4;            // experts of chunk j
    const int base1 = j * 4 + 32;       // experts of chunk j+8
    const float4 z4 = make_float4(0.0f, 0.0f, 0.0f, 0.0f);

    const int tok0 = blockIdx.x * 256 + (tid >> 3);
    const float4* nq = (const float4*)(noise + (size_t)tok0 * 64) + j;
    float4*       gq = (float4*)      (gates + (size_t)tok0 * 64) + j;
    const int*    tp = taskID + tok0;

    auto process = [&](const float4* nqi, float4* gqi, int t, unsigned mask) {
        gqi[0] = z4;
        gqi[8] = z4;
        const float4 n0 = nqi[0];
        const float4 n1 = nqi[8];

        const float4* cl4 = (const float4*)(s_cl + t * 64);
        const float4* st4 = (const float4*)(s_st + t * 64);
        const float4 c0 = cl4[j], c1 = cl4[j + 8];
        const float4 s0 = st4[j], s1 = st4[j + 8];

        const float l0 = fmaf(n0.x, s0.x, c0.x);
        const float l1 = fmaf(n0.y, s0.y, c0.y);
        const float l2 = fmaf(n0.z, s0.z, c0.z);
        const float l3 = fmaf(n0.w, s0.w, c0.w);
        const float l4 = fmaf(n1.x, s1.x, c1.x);
        const float l5 = fmaf(n1.y, s1.y, c1.y);
        const float l6 = fmaf(n1.z, s1.z, c1.z);
        const float l7 = fmaf(n1.w, s1.w, c1.w);

        // ---- local top-2: tournament tree ----
        // pairs (lo index first); '>= ' keeps earlier index on ties.
        const bool pa = l0 >= l1;
        const float a_hi = fmaxf(l0, l1), a_lo = fminf(l0, l1);
        const int a_hiI = pa ? base0     : base0 + 1;
        const int a_loI = pa ? base0 + 1 : base0;

        const bool pb = l2 >= l3;
        const float b_hi = fmaxf(l2, l3), b_lo = fminf(l2, l3);
        const int b_hiI = pb ? base0 + 2 : base0 + 3;
        const int b_loI = pb ? base0 + 3 : base0 + 2;

        const bool pc = l4 >= l5;
        const float c_hi = fmaxf(l4, l5), c_lo = fminf(l4, l5);
        const int c_hiI = pc ? base1     : base1 + 1;
        const int c_loI = pc ? base1 + 1 : base1;

        const bool pd = l6 >= l7;
        const float d_hi = fmaxf(l6, l7), d_lo = fminf(l6, l7);
        const int d_hiI = pd ? base1 + 2 : base1 + 3;
        const int d_loI = pd ? base1 + 3 : base1 + 2;

        // merge within each quad (A indices < B indices by construction)
        float q0v0, q0v1, q1v0, q1v1;
        int   q0i0, q0i1, q1i0, q1i1;
        merge_sorted_lowhi(a_hi, a_hiI, a_lo, a_loI,
                           b_hi, b_hiI, b_lo, b_loI,
                           q0v0, q0i0, q0v1, q0i1);
        merge_sorted_lowhi(c_hi, c_hiI, c_lo, c_loI,
                           d_hi, d_hiI, d_lo, d_loI,
                           q1v0, q1i0, q1v1, q1i1);

        // cross-quad merge (quad0 indices < quad1 indices)
        float v0, v1;
        int i0, i1;
        merge_sorted_lowhi(q0v0, q0i0, q0v1, q0i1,
                           q1v0, q1i0, q1v1, q1i1,
                           v0, i0, v1, i1);

        // ---- 3-step symmetric butterfly within the octet ----
        #pragma unroll
        for (int d = 1; d < 8; d <<= 1) {
            const float ov0 = __shfl_xor_sync(mask, v0, d, 8);
            const int   oi0 = __shfl_xor_sync(mask, i0, d, 8);
            const float ov1 = __shfl_xor_sync(mask, v1, d, 8);
            const int   oi1 = __shfl_xor_sync(mask, i1, d, 8);
            merge2(v0, i0, v1, i1, ov0, oi0, ov1, oi1);
        }

        // softmax over the top-2 (v0 >= v1 -> stable)
        const float e  = __expf(v1 - v0);
        const float ga = __fdividef(1.0f, 1.0f + e);
        const float gb = e * ga;

        // Patch stores: lane ((i>>2)&7)==j owns the quad it zeroed above;
        // same-thread program order => patch lands after the zero.
        float* grow = (float*)(gqi - j);
        if (((i0 >> 2) & 7) == j) grow[i0] = ga;
        if (((i1 >> 2) & 7) == j) grow[i1] = gb;

        if (j == 0) {
            atomicAdd(&s_load[i0], ga);
            atomicAdd(&s_load[i1], gb);
        }
    };

    if ((blockIdx.x + 1) * 256 <= (unsigned)B) {
        // Full block: unguarded, pointer-increment loop.
        #pragma unroll
        for (int it = 0; it < 8; ++it) {
            const int t = __ldg(tp);
            process(nq, gq, t, 0xffffffffu);
            nq += 512;          // 32 tokens * 16 float4
            gq += 512;
            tp += 32;
        }
    } else {
        // Tail block: guarded (condition uniform within each octet).
        int tok = tok0;
        for (int it = 0; it < 8; ++it) {
            const bool active = tok < B;
            const unsigned mask = __ballot_sync(0xffffffffu, active);
            if (active) {
                process(nq, gq, __ldg(tp), mask);
            }
            nq += 512;
            gq += 512;
            tp += 32;
            tok += 32;
        }
    }

    __syncthreads();
    if (tid < 64) atomicAdd(&loadv[tid], s_load[tid]);
}

// ---------------------------------------------------------------------------
// Launch
// ---------------------------------------------------------------------------
extern "C" void kernel_launch(void* const* d_in, const int* in_sizes, int n_in,
                              void* d_out, int out_size)
{
    const int*   taskID = (const int*)  d_in[0];
    const float* noise  = (const float*)d_in[1];
    const float* embed  = (const float*)d_in[2];
    const float* ekeys  = (const float*)d_in[3];
    const float* Wq     = (const float*)d_in[4];
    const float* bq     = (const float*)d_in[5];
    const float* Wk     = (const float*)d_in[6];
    const float* bk     = (const float*)d_in[7];
    const float* Wg     = (const float*)d_in[8];
    const float* bg     = (const float*)d_in[9];
    const float* Wn     = (const float*)d_in[10];
    const float* bn     = (const float*)d_in[11];

    const int B = in_sizes[0];
    float* gates = (float*)d_out;
    float* loadv = (float*)d_out + (out_size - 64);  // load tail

    precompute_kernel<<<6, 256>>>(embed, ekeys, Wq, bq, Wk, bk,
                                  Wg, bg, Wn, bn, loadv);

    const int blocks = (B + 255) / 256;
    gate_kernel<<<blocks, 256>>>(taskID, noise, gates, loadv, B);
}

// round 10
// speedup vs baseline: 3.2493x; 1.0028x over previous
#include <cuda_runtime.h>
#include <math.h>
#include <float.h>

// Per-task precomputed gating tables: only 6 distinct taskIDs exist.
__device__ float g_clean[6 * 64];
__device__ float g_std[6 * 64];

// ---------------------------------------------------------------------------
// Kernel 1: per-task precompute (6 blocks x 256 threads). All weights staged
// in shared with ROW STRIDE 33 (bank = (row+col)%32 -> conflict-free for the
// lane-varying-row GEMM reads below; staging writes also conflict-free).
// ---------------------------------------------------------------------------
__global__ __launch_bounds__(256) void precompute_kernel(
    const float* __restrict__ embed,   // (6, 32)
    const float* __restrict__ ekeys,   // (32, 32)
    const float* __restrict__ Wq,      // (32, 32)
    const float* __restrict__ bq,      // (32)
    const float* __restrict__ Wk,      // (32, 32)
    const float* __restrict__ bk,      // (32)
    const float* __restrict__ Wg,      // (64, 32)
    const float* __restrict__ bg,      // (64)
    const float* __restrict__ Wn,      // (64, 32)
    const float* __restrict__ bn,      // (64)
    float* __restrict__ load_out)      // (64) -> zero it
{
    const int t = blockIdx.x;
    const int tid = threadIdx.x;

    __shared__ float s_wq[32 * 33], s_wk[32 * 33], s_ek[32 * 33];
    __shared__ float s_k[32 * 33];
    __shared__ float s_wg[64 * 33], s_wn[64 * 33];
    __shared__ float s_q[32];
    __shared__ float s_ew[32];

    if (t == 0 && tid < 64) load_out[tid] = 0.0f;

    // Stage a 32x32 matrix padded to stride 33 (idx=4*tid is 4-aligned and
    // idx%32<=28, so all 4 elements share a row).
    {
        const int row = tid >> 3, col = (tid & 7) * 4;
        {
            const float4 v = ((const float4*)Wq)[tid];
            float* d = s_wq + row * 33 + col;
            d[0] = v.x; d[1] = v.y; d[2] = v.z; d[3] = v.w;
        }
        {
            const float4 v = ((const float4*)Wk)[tid];
            float* d = s_wk + row * 33 + col;
            d[0] = v.x; d[1] = v.y; d[2] = v.z; d[3] = v.w;
        }
        {
            const float4 v = ((const float4*)ekeys)[tid];
            float* d = s_ek + row * 33 + col;
            d[0] = v.x; d[1] = v.y; d[2] = v.z; d[3] = v.w;
        }
        #pragma unroll
        for (int rep = 0; rep < 2; rep++) {
            const int r2 = row + rep * 32;
            {
                const float4 v = ((const float4*)Wg)[tid + rep * 256];
                float* d = s_wg + r2 * 33 + col;
                d[0] = v.x; d[1] = v.y; d[2] = v.z; d[3] = v.w;
            }
            {
                const float4 v = ((const float4*)Wn)[tid + rep * 256];
                float* d = s_wn + r2 * 33 + col;
                d[0] = v.x; d[1] = v.y; d[2] = v.z; d[3] = v.w;
            }
        }
    }
    __syncthreads();

    // q = (embed[t] @ Wq^T + bq) * 1/sqrt(8)   (warp 0; reads conflict-free)
    if (tid < 32) {
        float acc = bq[tid];
        #pragma unroll
        for (int jj = 0; jj < 32; jj++)
            acc = fmaf(embed[t * 32 + jj], s_wq[tid * 33 + jj], acc);
        s_q[tid] = acc * 0.35355339059327373f;
    }

    // k = expert_keys @ Wk^T + bk  (1024 entries; 256 threads x 4)
    {
        const int p0 = tid * 4;
        #pragma unroll
        for (int q = 0; q < 4; q++) {
            const int p = p0 + q;
            const int s = p >> 5, i = p & 31;
            float acc = bk[i];
            #pragma unroll
            for (int jj = 0; jj < 32; jj++)
                acc = fmaf(s_ek[s * 33 + jj], s_wk[i * 33 + jj], acc);
            s_k[s * 33 + i] = acc;
        }
    }
    __syncthreads();

    // Warp 0 (lanes = experts s): scores, per-head softmax, mean, softmax.
    if (tid < 32) {
        float sc[4];
        #pragma unroll
        for (int h = 0; h < 4; h++) {
            float acc = 0.0f;
            #pragma unroll
            for (int d = 0; d < 8; d++)
                acc = fmaf(s_q[h * 8 + d], s_k[tid * 33 + h * 8 + d], acc);
            sc[h] = acc;
        }
        float aw = 0.0f;
        #pragma unroll
        for (int h = 0; h < 4; h++) {
            float m = sc[h];
            #pragma unroll
            for (int d = 16; d; d >>= 1)
                m = fmaxf(m, __shfl_xor_sync(0xffffffffu, m, d));
            float e = expf(sc[h] - m);
            float sum = e;
            #pragma unroll
            for (int d = 16; d; d >>= 1)
                sum += __shfl_xor_sync(0xffffffffu, sum, d);
            aw += 0.25f * (e / sum);
        }
        float m2 = aw;
        #pragma unroll
        for (int d = 16; d; d >>= 1)
            m2 = fmaxf(m2, __shfl_xor_sync(0xffffffffu, m2, d));
        float e2 = expf(aw - m2);
        float s2 = e2;
        #pragma unroll
        for (int d = 16; d; d >>= 1)
            s2 += __shfl_xor_sync(0xffffffffu, s2, d);
        s_ew[tid] = e2 / s2;
    }
    __syncthreads();

    // clean_logits[e], noise_std[e]; threads 0..63 (reads conflict-free)
    if (tid < 64) {
        float c = bg[tid];
        float nv = bn[tid];
        #pragma unroll
        for (int s = 0; s < 32; s++) {
            const float w = s_ew[s];
            c  = fmaf(w, s_wg[tid * 33 + s], c);
            nv = fmaf(w, s_wn[tid * 33 + s], nv);
        }
        g_clean[t * 64 + tid] = c;
        const float sp = (nv > 0.0f) ? (nv + log1pf(expf(-nv)))
                                     : log1pf(expf(nv));
        g_std[t * 64 + tid] = sp + 0.01f;
    }
}

// ---------------------------------------------------------------------------
// Merge two SORTED top-2 pairs where ALL indices of pair A are lower than all
// indices of pair B. Ties then need only '>=' (prefers the lower-index side).
// ---------------------------------------------------------------------------
__device__ __forceinline__ void merge_sorted_lowhi(
    float a0, int ia0, float a1, int ia1,
    float b0, int ib0, float b1, int ib1,
    float& v0, int& i0, float& v1, int& i1)
{
    const bool p = a0 >= b0;
    v0 = fmaxf(a0, b0);
    i0 = p ? ia0 : ib0;
    const float x  = p ? a1 : a0;   // A-side candidate (lower index)
    const int   xi = p ? ia1 : ia0;
    const float y  = p ? b0 : b1;
    const int   yi = p ? ib0 : ib1;
    const bool q = x >= y;
    v1 = fmaxf(x, y);
    i1 = q ? xi : yi;
}

// ---------------------------------------------------------------------------
// Branchless symmetric merge of two sorted top-2 pairs under the total order
// (value desc, index asc). Both sides of a butterfly compute identical output.
// ---------------------------------------------------------------------------
__device__ __forceinline__ void merge2(float& v0, int& i0, float& v1, int& i1,
                                       float ov0, int oi0, float ov1, int oi1)
{
    const bool fw = (v0 > ov0) || (v0 == ov0 && i0 < oi0);
    const float w0  = fw ? v0  : ov0;
    const int   w0i = fw ? i0  : oi0;
    const float c   = fw ? ov0 : v0;
    const int   ci  = fw ? oi0 : i0;
    const float b   = fw ? v1  : ov1;
    const int   bi  = fw ? i1  : oi1;
    const bool  w   = (c > b) || (c == b && ci < bi);
    v0 = w0;  i0 = w0i;
    v1 = w ? c  : b;
    i1 = w ? ci : bi;
}

// ---------------------------------------------------------------------------
// Kernel 2: per-token gating, 8 lanes per token (perfect 128B coalescing).
// Gates quads are built in registers and written with ONE STG.128 pair
// (no zero+patch second touch of the lines).
// ---------------------------------------------------------------------------
__global__ __launch_bounds__(256) void gate_kernel(
    const int*   __restrict__ taskID,
    const float* __restrict__ noise,
    float*       __restrict__ gates,
    float*       __restrict__ loadv,
    int B)
{
    __shared__ float s_cl[6 * 64];
    __shared__ float s_st[6 * 64];
    __shared__ float s_load[64];

    const int tid = threadIdx.x;
    if (tid < 64) s_load[tid] = 0.0f;
    for (int i = tid; i < 6 * 64; i += 256) {
        s_cl[i] = g_clean[i];
        s_st[i] = g_std[i];
    }
    __syncthreads();

    const int j = tid & 7;              // lane within octet
    const int oct4 = (tid >> 3) & 3;    // octet within warp
    const int base0 = j * 4;            // experts of chunk j
    const int base1 = j * 4 + 32;       // experts of chunk j+8

    const int tok0 = blockIdx.x * 256 + (tid >> 3);
    const float4* nq = (const float4*)(noise + (size_t)tok0 * 64) + j;
    float4*       gq = (float4*)      (gates + (size_t)tok0 * 64) + j;

    auto process = [&](const float4* nqi, float4* gqi, int t, unsigned mask) {
        const float4 n0 = nqi[0];
        const float4 n1 = nqi[8];

        const float4* cl4 = (const float4*)(s_cl + t * 64);
        const float4* st4 = (const float4*)(s_st + t * 64);
        const float4 c0 = cl4[j], c1 = cl4[j + 8];
        const float4 s0 = st4[j], s1 = st4[j + 8];

        const float l0 = fmaf(n0.x, s0.x, c0.x);
        const float l1 = fmaf(n0.y, s0.y, c0.y);
        const float l2 = fmaf(n0.z, s0.z, c0.z);
        const float l3 = fmaf(n0.w, s0.w, c0.w);
        const float l4 = fmaf(n1.x, s1.x, c1.x);
        const float l5 = fmaf(n1.y, s1.y, c1.y);
        const float l6 = fmaf(n1.z, s1.z, c1.z);
        const float l7 = fmaf(n1.w, s1.w, c1.w);

        // ---- local top-2: tournament tree (>= keeps earlier index) ----
        const bool pa = l0 >= l1;
        const float a_hi = fmaxf(l0, l1), a_lo = fminf(l0, l1);
        const int a_hiI = pa ? base0     : base0 + 1;
        const int a_loI = pa ? base0 + 1 : base0;

        const bool pb = l2 >= l3;
        const float b_hi = fmaxf(l2, l3), b_lo = fminf(l2, l3);
        const int b_hiI = pb ? base0 + 2 : base0 + 3;
        const int b_loI = pb ? base0 + 3 : base0 + 2;

        const bool pc = l4 >= l5;
        const float c_hi = fmaxf(l4, l5), c_lo = fminf(l4, l5);
        const int c_hiI = pc ? base1     : base1 + 1;
        const int c_loI = pc ? base1 + 1 : base1;

        const bool pd = l6 >= l7;
        const float d_hi = fmaxf(l6, l7), d_lo = fminf(l6, l7);
        const int d_hiI = pd ? base1 + 2 : base1 + 3;
        const int d_loI = pd ? base1 + 3 : base1 + 2;

        float q0v0, q0v1, q1v0, q1v1;
        int   q0i0, q0i1, q1i0, q1i1;
        merge_sorted_lowhi(a_hi, a_hiI, a_lo, a_loI,
                           b_hi, b_hiI, b_lo, b_loI,
                           q0v0, q0i0, q0v1, q0i1);
        merge_sorted_lowhi(c_hi, c_hiI, c_lo, c_loI,
                           d_hi, d_hiI, d_lo, d_loI,
                           q1v0, q1i0, q1v1, q1i1);

        float v0, v1;
        int i0, i1;
        merge_sorted_lowhi(q0v0, q0i0, q0v1, q0i1,
                           q1v0, q1i0, q1v1, q1i1,
                           v0, i0, v1, i1);

        // ---- 3-step symmetric butterfly within the octet ----
        #pragma unroll
        for (int d = 1; d < 8; d <<= 1) {
            const float ov0 = __shfl_xor_sync(mask, v0, d, 8);
            const int   oi0 = __shfl_xor_sync(mask, i0, d, 8);
            const float ov1 = __shfl_xor_sync(mask, v1, d, 8);
            const int   oi1 = __shfl_xor_sync(mask, i1, d, 8);
            merge2(v0, i0, v1, i1, ov0, oi0, ov1, oi1);
        }

        // softmax over the top-2 (v0 >= v1 -> stable)
        const float e  = __expf(v1 - v0);
        const float ga = __fdividef(1.0f, 1.0f + e);
        const float gb = e * ga;

        // Build both owned quads in registers; single STG.128 each.
        float4 o0, o1;
        o0.x = (base0 + 0 == i0) ? ga : ((base0 + 0 == i1) ? gb : 0.0f);
        o0.y = (base0 + 1 == i0) ? ga : ((base0 + 1 == i1) ? gb : 0.0f);
        o0.z = (base0 + 2 == i0) ? ga : ((base0 + 2 == i1) ? gb : 0.0f);
        o0.w = (base0 + 3 == i0) ? ga : ((base0 + 3 == i1) ? gb : 0.0f);
        o1.x = (base1 + 0 == i0) ? ga : ((base1 + 0 == i1) ? gb : 0.0f);
        o1.y = (base1 + 1 == i0) ? ga : ((base1 + 1 == i1) ? gb : 0.0f);
        o1.z = (base1 + 2 == i0) ? ga : ((base1 + 2 == i1) ? gb : 0.0f);
        o1.w = (base1 + 3 == i0) ? ga : ((base1 + 3 == i1) ? gb : 0.0f);
        gqi[0] = o0;
        gqi[8] = o1;

        if (j == 0) {
            atomicAdd(&s_load[i0], ga);
            atomicAdd(&s_load[i1], gb);
        }
    };

    if ((blockIdx.x + 1) * 256 <= (unsigned)B) {
        // taskID preload: lane l holds task of token (warp*4 + (l&3) + 32*(l>>2))
        const int lane = tid & 31;
        const int pre = blockIdx.x * 256 + ((tid >> 5) << 2) +
                        (lane & 3) + ((lane >> 2) << 5);
        const int tval = __ldg(taskID + pre);
        const float4* nqi = nq;
        float4* gqi = gq;
        #pragma unroll
        for (int it = 0; it < 8; ++it) {
            const int t = __shfl_sync(0xffffffffu, tval, it * 4 + oct4, 32);
            process(nqi, gqi, t, 0xffffffffu);
            nqi += 512;          // 32 tokens * 16 float4
            gqi += 512;
        }
    } else {
        // Tail block: guarded (condition uniform within each octet).
        const int* tp = taskID + tok0;
        const float4* nqi = nq;
        float4* gqi = gq;
        int tok = tok0;
        for (int it = 0; it < 8; ++it) {
            const bool active = tok < B;
            const unsigned mask = __ballot_sync(0xffffffffu, active);
            if (active) {
                process(nqi, gqi, __ldg(tp), mask);
            }
            nqi += 512;
            gqi += 512;
            tp += 32;
            tok += 32;
        }
    }

    __syncthreads();
    if (tid < 64) atomicAdd(&loadv[tid], s_load[tid]);
}

// ---------------------------------------------------------------------------
// Launch
// ---------------------------------------------------------------------------
extern "C" void kernel_launch(void* const* d_in, const int* in_sizes, int n_in,
                              void* d_out, int out_size)
{
    const int*   taskID = (const int*)  d_in[0];
    const float* noise  = (const float*)d_in[1];
    const float* embed  = (const float*)d_in[2];
    const float* ekeys  = (const float*)d_in[3];
    const float* Wq     = (const float*)d_in[4];
    const float* bq     = (const float*)d_in[5];
    const float* Wk     = (const float*)d_in[6];
    const float* bk     = (const float*)d_in[7];
    const float* Wg     = (const float*)d_in[8];
    const float* bg     = (const float*)d_in[9];
    const float* Wn     = (const float*)d_in[10];
    const float* bn     = (const float*)d_in[11];

    const int B = in_sizes[0];
    float* gates = (float*)d_out;
    float* loadv = (float*)d_out + (out_size - 64);  // load tail

    precompute_kernel<<<6, 256>>>(embed, ekeys, Wq, bq, Wk, bk,
                                  Wg, bg, Wn, bn, loadv);

    const int blocks = (B + 255) / 256;
    gate_kernel<<<blocks, 256>>>(taskID, noise, gates, loadv, B);
}

// round 11
// speedup vs baseline: 3.3951x; 1.0449x over previous
#include <cuda_runtime.h>
#include <math.h>
#include <float.h>

// Per-task precomputed gating tables: only 6 distinct taskIDs exist.
__device__ float g_clean[6 * 64];
__device__ float g_std[6 * 64];

// ---------------------------------------------------------------------------
// Kernel 1: per-task precompute (6 blocks x 256 threads). All weights staged
// in shared with ROW STRIDE 33 (bank = (row+col)%32 -> conflict-free for the
// lane-varying-row GEMM reads below; staging writes also conflict-free).
// ---------------------------------------------------------------------------
__global__ __launch_bounds__(256) void precompute_kernel(
    const float* __restrict__ embed,   // (6, 32)
    const float* __restrict__ ekeys,   // (32, 32)
    const float* __restrict__ Wq,      // (32, 32)
    const float* __restrict__ bq,      // (32)
    const float* __restrict__ Wk,      // (32, 32)
    const float* __restrict__ bk,      // (32)
    const float* __restrict__ Wg,      // (64, 32)
    const float* __restrict__ bg,      // (64)
    const float* __restrict__ Wn,      // (64, 32)
    const float* __restrict__ bn,      // (64)
    float* __restrict__ load_out)      // (64) -> zero it
{
    const int t = blockIdx.x;
    const int tid = threadIdx.x;

    __shared__ float s_wq[32 * 33], s_wk[32 * 33], s_ek[32 * 33];
    __shared__ float s_k[32 * 33];
    __shared__ float s_wg[64 * 33], s_wn[64 * 33];
    __shared__ float s_q[32];
    __shared__ float s_ew[32];

    if (t == 0 && tid < 64) load_out[tid] = 0.0f;

    // Stage a 32x32 matrix padded to stride 33.
    {
        const int row = tid >> 3, col = (tid & 7) * 4;
        {
            const float4 v = ((const float4*)Wq)[tid];
            float* d = s_wq + row * 33 + col;
            d[0] = v.x; d[1] = v.y; d[2] = v.z; d[3] = v.w;
        }
        {
            const float4 v = ((const float4*)Wk)[tid];
            float* d = s_wk + row * 33 + col;
            d[0] = v.x; d[1] = v.y; d[2] = v.z; d[3] = v.w;
        }
        {
            const float4 v = ((const float4*)ekeys)[tid];
            float* d = s_ek + row * 33 + col;
            d[0] = v.x; d[1] = v.y; d[2] = v.z; d[3] = v.w;
        }
        #pragma unroll
        for (int rep = 0; rep < 2; rep++) {
            const int r2 = row + rep * 32;
            {
                const float4 v = ((const float4*)Wg)[tid + rep * 256];
                float* d = s_wg + r2 * 33 + col;
                d[0] = v.x; d[1] = v.y; d[2] = v.z; d[3] = v.w;
            }
            {
                const float4 v = ((const float4*)Wn)[tid + rep * 256];
                float* d = s_wn + r2 * 33 + col;
                d[0] = v.x; d[1] = v.y; d[2] = v.z; d[3] = v.w;
            }
        }
    }
    __syncthreads();

    // q = (embed[t] @ Wq^T + bq) * 1/sqrt(8)   (warp 0; reads conflict-free)
    if (tid < 32) {
        float acc = bq[tid];
        #pragma unroll
        for (int jj = 0; jj < 32; jj++)
            acc = fmaf(embed[t * 32 + jj], s_wq[tid * 33 + jj], acc);
        s_q[tid] = acc * 0.35355339059327373f;
    }

    // k = expert_keys @ Wk^T + bk  (1024 entries; 256 threads x 4)
    {
        const int p0 = tid * 4;
        #pragma unroll
        for (int q = 0; q < 4; q++) {
            const int p = p0 + q;
            const int s = p >> 5, i = p & 31;
            float acc = bk[i];
            #pragma unroll
            for (int jj = 0; jj < 32; jj++)
                acc = fmaf(s_ek[s * 33 + jj], s_wk[i * 33 + jj], acc);
            s_k[s * 33 + i] = acc;
        }
    }
    __syncthreads();

    // Warp 0 (lanes = experts s): scores, per-head softmax, mean, softmax.
    if (tid < 32) {
        float sc[4];
        #pragma unroll
        for (int h = 0; h < 4; h++) {
            float acc = 0.0f;
            #pragma unroll
            for (int d = 0; d < 8; d++)
                acc = fmaf(s_q[h * 8 + d], s_k[tid * 33 + h * 8 + d], acc);
            sc[h] = acc;
        }
        float aw = 0.0f;
        #pragma unroll
        for (int h = 0; h < 4; h++) {
            float m = sc[h];
            #pragma unroll
            for (int d = 16; d; d >>= 1)
                m = fmaxf(m, __shfl_xor_sync(0xffffffffu, m, d));
            float e = expf(sc[h] - m);
            float sum = e;
            #pragma unroll
            for (int d = 16; d; d >>= 1)
                sum += __shfl_xor_sync(0xffffffffu, sum, d);
            aw += 0.25f * (e / sum);
        }
        float m2 = aw;
        #pragma unroll
        for (int d = 16; d; d >>= 1)
            m2 = fmaxf(m2, __shfl_xor_sync(0xffffffffu, m2, d));
        float e2 = expf(aw - m2);
        float s2 = e2;
        #pragma unroll
        for (int d = 16; d; d >>= 1)
            s2 += __shfl_xor_sync(0xffffffffu, s2, d);
        s_ew[tid] = e2 / s2;
    }
    __syncthreads();

    // clean_logits[e], noise_std[e]; threads 0..63 (reads conflict-free)
    if (tid < 64) {
        float c = bg[tid];
        float nv = bn[tid];
        #pragma unroll
        for (int s = 0; s < 32; s++) {
            const float w = s_ew[s];
            c  = fmaf(w, s_wg[tid * 33 + s], c);
            nv = fmaf(w, s_wn[tid * 33 + s], nv);
        }
        g_clean[t * 64 + tid] = c;
        const float sp = (nv > 0.0f) ? (nv + log1pf(expf(-nv)))
                                     : log1pf(expf(nv));
        g_std[t * 64 + tid] = sp + 0.01f;
    }
}

// ---------------------------------------------------------------------------
// Merge two SORTED top-2 pairs where ALL indices of pair A are lower than all
// indices of pair B. Ties then need only '>=' (prefers the lower-index side).
// ---------------------------------------------------------------------------
__device__ __forceinline__ void merge_sorted_lowhi(
    float a0, int ia0, float a1, int ia1,
    float b0, int ib0, float b1, int ib1,
    float& v0, int& i0, float& v1, int& i1)
{
    const bool p = a0 >= b0;
    v0 = fmaxf(a0, b0);
    i0 = p ? ia0 : ib0;
    const float x  = p ? a1 : a0;   // A-side candidate (lower index)
    const int   xi = p ? ia1 : ia0;
    const float y  = p ? b0 : b1;
    const int   yi = p ? ib0 : ib1;
    const bool q = x >= y;
    v1 = fmaxf(x, y);
    i1 = q ? xi : yi;
}

// ---------------------------------------------------------------------------
// Branchless symmetric merge of two sorted top-2 pairs under the total order
// (value desc, index asc). Both sides of a butterfly compute identical output.
// ---------------------------------------------------------------------------
__device__ __forceinline__ void merge2(float& v0, int& i0, float& v1, int& i1,
                                       float ov0, int oi0, float ov1, int oi1)
{
    const bool fw = (v0 > ov0) || (v0 == ov0 && i0 < oi0);
    const float w0  = fw ? v0  : ov0;
    const int   w0i = fw ? i0  : oi0;
    const float c   = fw ? ov0 : v0;
    const int   ci  = fw ? oi0 : i0;
    const float b   = fw ? v1  : ov1;
    const int   bi  = fw ? i1  : oi1;
    const bool  w   = (c > b) || (c == b && ci < bi);
    v0 = w0;  i0 = w0i;
    v1 = w ? c  : b;
    i1 = w ? ci : bi;
}

// ---------------------------------------------------------------------------
// Kernel 2: per-token gating, 8 lanes per token (perfect 128B coalescing).
// Local top-2 via tournament tree; zero-quad + owner-lane patch stores
// (R9 configuration: 32 regs, ~86% occupancy — best measured).
// ---------------------------------------------------------------------------
__global__ __launch_bounds__(256) void gate_kernel(
    const int*   __restrict__ taskID,
    const float* __restrict__ noise,
    float*       __restrict__ gates,
    float*       __restrict__ loadv,
    int B)
{
    __shared__ float s_cl[6 * 64];
    __shared__ float s_st[6 * 64];
    __shared__ float s_load[64];

    const int tid = threadIdx.x;
    if (tid < 64) s_load[tid] = 0.0f;
    for (int i = tid; i < 6 * 64; i += 256) {
        s_cl[i] = g_clean[i];
        s_st[i] = g_std[i];
    }
    __syncthreads();

    const int j = tid & 7;              // lane within octet
    const int base0 = j * 4;            // experts of chunk j
    const int base1 = j * 4 + 32;       // experts of chunk j+8
    const float4 z4 = make_float4(0.0f, 0.0f, 0.0f, 0.0f);

    const int tok0 = blockIdx.x * 256 + (tid >> 3);
    const float4* nq = (const float4*)(noise + (size_t)tok0 * 64) + j;
    float4*       gq = (float4*)      (gates + (size_t)tok0 * 64) + j;
    const int*    tp = taskID + tok0;

    auto process = [&](const float4* nqi, float4* gqi, int t, unsigned mask) {
        gqi[0] = z4;
        gqi[8] = z4;
        const float4 n0 = nqi[0];
        const float4 n1 = nqi[8];

        const float4* cl4 = (const float4*)(s_cl + t * 64);
        const float4* st4 = (const float4*)(s_st + t * 64);
        const float4 c0 = cl4[j], c1 = cl4[j + 8];
        const float4 s0 = st4[j], s1 = st4[j + 8];

        const float l0 = fmaf(n0.x, s0.x, c0.x);
        const float l1 = fmaf(n0.y, s0.y, c0.y);
        const float l2 = fmaf(n0.z, s0.z, c0.z);
        const float l3 = fmaf(n0.w, s0.w, c0.w);
        const float l4 = fmaf(n1.x, s1.x, c1.x);
        const float l5 = fmaf(n1.y, s1.y, c1.y);
        const float l6 = fmaf(n1.z, s1.z, c1.z);
        const float l7 = fmaf(n1.w, s1.w, c1.w);

        // ---- local top-2: tournament tree (>= keeps earlier index) ----
        const bool pa = l0 >= l1;
        const float a_hi = fmaxf(l0, l1), a_lo = fminf(l0, l1);
        const int a_hiI = pa ? base0     : base0 + 1;
        const int a_loI = pa ? base0 + 1 : base0;

        const bool pb = l2 >= l3;
        const float b_hi = fmaxf(l2, l3), b_lo = fminf(l2, l3);
        const int b_hiI = pb ? base0 + 2 : base0 + 3;
        const int b_loI = pb ? base0 + 3 : base0 + 2;

        const bool pc = l4 >= l5;
        const float c_hi = fmaxf(l4, l5), c_lo = fminf(l4, l5);
        const int c_hiI = pc ? base1     : base1 + 1;
        const int c_loI = pc ? base1 + 1 : base1;

        const bool pd = l6 >= l7;
        const float d_hi = fmaxf(l6, l7), d_lo = fminf(l6, l7);
        const int d_hiI = pd ? base1 + 2 : base1 + 3;
        const int d_loI = pd ? base1 + 3 : base1 + 2;

        float q0v0, q0v1, q1v0, q1v1;
        int   q0i0, q0i1, q1i0, q1i1;
        merge_sorted_lowhi(a_hi, a_hiI, a_lo, a_loI,
                           b_hi, b_hiI, b_lo, b_loI,
                           q0v0, q0i0, q0v1, q0i1);
        merge_sorted_lowhi(c_hi, c_hiI, c_lo, c_loI,
                           d_hi, d_hiI, d_lo, d_loI,
                           q1v0, q1i0, q1v1, q1i1);

        float v0, v1;
        int i0, i1;
        merge_sorted_lowhi(q0v0, q0i0, q0v1, q0i1,
                           q1v0, q1i0, q1v1, q1i1,
                           v0, i0, v1, i1);

        // ---- 3-step symmetric butterfly within the octet ----
        #pragma unroll
        for (int d = 1; d < 8; d <<= 1) {
            const float ov0 = __shfl_xor_sync(mask, v0, d, 8);
            const int   oi0 = __shfl_xor_sync(mask, i0, d, 8);
            const float ov1 = __shfl_xor_sync(mask, v1, d, 8);
            const int   oi1 = __shfl_xor_sync(mask, i1, d, 8);
            merge2(v0, i0, v1, i1, ov0, oi0, ov1, oi1);
        }

        // softmax over the top-2 (v0 >= v1 -> stable)
        const float e  = __expf(v1 - v0);
        const float ga = __fdividef(1.0f, 1.0f + e);
        const float gb = e * ga;

        // Patch stores: lane ((i>>2)&7)==j owns the quad it zeroed above;
        // same-thread program order => patch lands after the zero.
        float* grow = (float*)(gqi - j);
        if (((i0 >> 2) & 7) == j) grow[i0] = ga;
        if (((i1 >> 2) & 7) == j) grow[i1] = gb;

        if (j == 0) {
            atomicAdd(&s_load[i0], ga);
            atomicAdd(&s_load[i1], gb);
        }
    };

    if ((blockIdx.x + 1) * 256 <= (unsigned)B) {
        // Full block: unguarded, pointer-increment loop.
        #pragma unroll
        for (int it = 0; it < 8; ++it) {
            const int t = __ldg(tp);
            process(nq, gq, t, 0xffffffffu);
            nq += 512;          // 32 tokens * 16 float4
            gq += 512;
            tp += 32;
        }
    } else {
        // Tail block: guarded (condition uniform within each octet).
        int tok = tok0;
        for (int it = 0; it < 8; ++it) {
            const bool active = tok < B;
            const unsigned mask = __ballot_sync(0xffffffffu, active);
            if (active) {
                process(nq, gq, __ldg(tp), mask);
            }
            nq += 512;
            gq += 512;
            tp += 32;
            tok += 32;
        }
    }

    __syncthreads();
    if (tid < 64) atomicAdd(&loadv[tid], s_load[tid]);
}

// ---------------------------------------------------------------------------
// Launch
// ---------------------------------------------------------------------------
extern "C" void kernel_launch(void* const* d_in, const int* in_sizes, int n_in,
                              void* d_out, int out_size)
{
    const int*   taskID = (const int*)  d_in[0];
    const float* noise  = (const float*)d_in[1];
    const float* embed  = (const float*)d_in[2];
    const float* ekeys  = (const float*)d_in[3];
    const float* Wq     = (const float*)d_in[4];
    const float* bq     = (const float*)d_in[5];
    const float* Wk     = (const float*)d_in[6];
    const float* bk     = (const float*)d_in[7];
    const float* Wg     = (const float*)d_in[8];
    const float* bg     = (const float*)d_in[9];
    const float* Wn     = (const float*)d_in[10];
    const float* bn     = (const float*)d_in[11];

    const int B = in_sizes[0];
    float* gates = (float*)d_out;
    float* loadv = (float*)d_out + (out_size - 64);  // load tail

    precompute_kernel<<<6, 256>>>(embed, ekeys, Wq, bq, Wk, bk,
                                  Wg, bg, Wn, bn, loadv);

    const int blocks = (B + 255) / 256;
    gate_kernel<<<blocks, 256>>>(taskID, noise, gates, loadv, B);
}